// round 17
// baseline (speedup 1.0000x reference)
#include <cuda_runtime.h>
#include <cuda_fp16.h>
#include <cstdint>

// VQVAE nearest-codebook: fp16 mma.sync fast scores + warp-parallel exact fp32
// rescore. Persistent CTAs; q-major LDS.128 codebook layout.
// z:[131072,64] f32, cb:[512,64] f32. out = (gather, gather).

#define Dm 64
#define Kc 512
#define ROWS_CTA 512
#define THREADS 512
#define NTILES 64
#define MARGIN 2e-3f
#define QCAP 256
#define GRID 152
#define BPITCH 44

// ---- smem layout (bytes) ----
#define SM_ZHW  0                      // 512 x 36 u32 f16x2(-2z), pitch 36       73728
#define SM_BSW  73728                  // 512 x 44 u32 codebook q-major           90112
#define SM_TMIN 163840                 // 16 warps x 64 tiles x 8 rg, fp16        16384
#define SM_EEF  180224                 // 512 f32 exact ee                         2048
#define SM_EEQ  182272                 // 256 u32 ee half2, [q][t] order           1024
#define SM_ZZS  183296                 // 512 f32 exact zz                         2048
#define SM_MINR 185344                 // 512 u64 (score_bits<<32 | j)             4096
#define SM_QCNT 189440                 // 16 i32 (+pad)                             128
#define SM_WFLG 189568                 // 16 i32 overflow flags                     128
#define SM_QUE  189696                 // 16 x 256 u32 candidates                 16384
#define SM_TOTAL 206080

__device__ __forceinline__ void mma16816h(unsigned& c01, unsigned& c23,
                                          unsigned a0, unsigned a1, unsigned a2, unsigned a3,
                                          unsigned b0, unsigned b1) {
    asm volatile("mma.sync.aligned.m16n8k16.row.col.f16.f16.f16.f16 "
                 "{%0,%1},{%2,%3,%4,%5},{%6,%7},{%0,%1};"
                 : "+r"(c01), "+r"(c23)
                 : "r"(a0), "r"(a1), "r"(a2), "r"(a3), "r"(b0), "r"(b1));
}

__device__ __forceinline__ unsigned hmin2u(unsigned x, unsigned y) {
    __half2 r = __hmin2(*(__half2*)&x, *(__half2*)&y);
    return *(unsigned*)&r;
}

// Exact rescore (sequential fp32, matches reference rounding) + 64-bit atomicMin
// commit. key=(score_bits<<32)|j: scores >= 0 so bit order == value order;
// ties resolve to smallest j (first-index, as jnp.argmin).
__device__ __noinline__ void exact_commit(unsigned pk, const float* __restrict__ z,
                                          const float* __restrict__ cb, size_t blockRow,
                                          const float* zzs, const float* eef,
                                          unsigned long long* minr) {
    int row = pk & 511;
    int j = pk >> 9;
    const float4* zp = (const float4*)(z + (blockRow + row) * Dm);
    const float4* ep = (const float4*)(cb + (size_t)j * Dm);
    float dot = 0.0f;
#pragma unroll
    for (int i = 0; i < 16; ++i) {
        float4 a = __ldg(zp + i);
        float4 b = __ldg(ep + i);
        dot = __fmaf_rn(a.x, b.x, dot);
        dot = __fmaf_rn(a.y, b.y, dot);
        dot = __fmaf_rn(a.z, b.z, dot);
        dot = __fmaf_rn(a.w, b.w, dot);
    }
    float sx = __fadd_rn(__fadd_rn(zzs[row], eef[j]), __fmul_rn(-2.0f, dot));
    unsigned long long key = ((unsigned long long)__float_as_uint(sx) << 32) | (unsigned)j;
    atomicMin(minr + row, key);
}

// One tile body: 2x LDS.128 B + 8 HMMA. Scores c01(rows ra),c23(ra+8),c45(+16),c67(+24).
#define TILE_BODY(tv, einit, c01, c23, c45, c67) do {                              \
        const uint4* bp_ = (const uint4*)(bsw + ((tv) * 8 + rg) * BPITCH + 8 * q); \
        uint4 B0 = bp_[0], B1 = bp_[1];                                            \
        c01 = (einit); c23 = (einit); c45 = (einit); c67 = (einit);                \
        mma16816h(c01, c23, a[0], a[1], a[2], a[3], B0.x, B0.y);                   \
        mma16816h(c01, c23, a[4], a[5], a[6], a[7], B0.z, B0.w);                   \
        mma16816h(c01, c23, a[8], a[9], a[10], a[11], B1.x, B1.y);                 \
        mma16816h(c01, c23, a[12], a[13], a[14], a[15], B1.z, B1.w);               \
        mma16816h(c45, c67, a[16], a[17], a[18], a[19], B0.x, B0.y);               \
        mma16816h(c45, c67, a[20], a[21], a[22], a[23], B0.z, B0.w);               \
        mma16816h(c45, c67, a[24], a[25], a[26], a[27], B1.x, B1.y);               \
        mma16816h(c45, c67, a[28], a[29], a[30], a[31], B1.z, B1.w);               \
    } while (0)

__global__ void __launch_bounds__(THREADS, 1)
vq_kernel(const float* __restrict__ z, const float* __restrict__ cb,
          float* __restrict__ out, long long half, int nblk) {
    extern __shared__ char sm[];
    unsigned* zhw = (unsigned*)(sm + SM_ZHW);
    unsigned* bsw = (unsigned*)(sm + SM_BSW);
    __half* tminp = (__half*)(sm + SM_TMIN);
    float* eef = (float*)(sm + SM_EEF);
    unsigned* eeq = (unsigned*)(sm + SM_EEQ);
    float* zzs = (float*)(sm + SM_ZZS);
    unsigned long long* minr = (unsigned long long*)(sm + SM_MINR);
    int* qcnt = (int*)(sm + SM_QCNT);
    int* wflg = (int*)(sm + SM_WFLG);
    unsigned* que = (unsigned*)(sm + SM_QUE);

    const int tid = threadIdx.x, lane = tid & 31, wid = tid >> 5;
    const int q = lane & 3, rg = lane >> 2;

    // ---------------- prolog B (ONCE): codebook row tid -> exact ee + q-major f16 ------
    // Position p (0..31) holds original f16x2 word w = (p>>3) + 4*(p&1) + 8*((p&7)>>1),
    // i.e. thread-quad q reads its 4 k-step (b0,b1) pairs as words [8q..8q+8) ->
    // two LDS.128. Chunk c covers k-steps {2c,2c+1} using only er[8c..8c+8).
    {
        const float4* er = (const float4*)(cb + (size_t)tid * Dm);
        float s = 0.0f;
#pragma unroll
        for (int c = 0; c < 2; ++c) {
            float4 ev[8];
#pragma unroll
            for (int i = 0; i < 8; ++i) ev[i] = er[c * 8 + i];
#pragma unroll
            for (int i = 0; i < 8; ++i) {
                s = __fadd_rn(s, __fmul_rn(ev[i].x, ev[i].x));
                s = __fadd_rn(s, __fmul_rn(ev[i].y, ev[i].y));
                s = __fadd_rn(s, __fmul_rn(ev[i].z, ev[i].z));
                s = __fadd_rn(s, __fmul_rn(ev[i].w, ev[i].w));
            }
#pragma unroll
            for (int qq = 0; qq < 4; ++qq) {
                unsigned pw[4];
#pragma unroll
                for (int u = 0; u < 4; ++u) {
                    // u = 2*(ks - 2c) + i; w = qq + 4*i + 8*ks
                    int ks = 2 * c + (u >> 1), i = u & 1;
                    int w = qq + 4 * i + 8 * ks;
                    float4 f = ev[(w >> 1) - c * 8];
                    float lo = (w & 1) ? f.z : f.x;
                    float hi = (w & 1) ? f.w : f.y;
                    __half2 b = __float22half2_rn(make_float2(lo, hi));
                    pw[u] = *(unsigned*)&b;
                }
                ((uint4*)(bsw + tid * BPITCH))[2 * qq + c] =
                    make_uint4(pw[0], pw[1], pw[2], pw[3]);
            }
        }
        eef[tid] = s;
        // eeq[q'][t'] layout: pair m = tid>>1 (codes 2m,2m+1) stored at (m&3)*64 + (m>>2)
        float so = __shfl_xor_sync(0xffffffffu, s, 1);
        if (!(tid & 1)) {
            __half2 h2 = __halves2half2(__float2half_rn(s), __float2half_rn(so));
            int m = tid >> 1;
            eeq[(m & 3) * 64 + (m >> 2)] = *(unsigned*)&h2;
        }
    }

    // ================ persistent loop over row-blocks ================
    for (int blk = blockIdx.x; blk < nblk; blk += GRID) {
        const size_t blockRow = (size_t)blk * ROWS_CTA;
        __syncthreads();                         // prior block fully consumed
        if (tid < 16) { qcnt[tid] = 0; wflg[tid] = 0; }
        minr[tid] = ~0ull;

        // ---- prolog A: z row -> exact zz + f16(-2z), chunked ----
        {
            const float4* zr = (const float4*)(z + (blockRow + tid) * Dm);
            float zz = 0.0f;
#pragma unroll
            for (int c = 0; c < 2; ++c) {
                float4 v[8];
#pragma unroll
                for (int i = 0; i < 8; ++i) v[i] = zr[c * 8 + i];
#pragma unroll
                for (int i = 0; i < 8; ++i) {
                    zz = __fadd_rn(zz, __fmul_rn(v[i].x, v[i].x));
                    zz = __fadd_rn(zz, __fmul_rn(v[i].y, v[i].y));
                    zz = __fadd_rn(zz, __fmul_rn(v[i].z, v[i].z));
                    zz = __fadd_rn(zz, __fmul_rn(v[i].w, v[i].w));
                }
                unsigned p[16];
#pragma unroll
                for (int i = 0; i < 8; ++i) {
                    __half2 b0 = __float22half2_rn(make_float2(-2.f * v[i].x, -2.f * v[i].y));
                    __half2 b1 = __float22half2_rn(make_float2(-2.f * v[i].z, -2.f * v[i].w));
                    p[2 * i] = *(unsigned*)&b0;
                    p[2 * i + 1] = *(unsigned*)&b1;
                }
                uint4* d4 = (uint4*)(zhw + tid * 36) + c * 4;
#pragma unroll
                for (int i = 0; i < 4; ++i) d4[i] = make_uint4(p[4 * i], p[4 * i + 1], p[4 * i + 2], p[4 * i + 3]);
            }
            zzs[tid] = zz;
        }
        __syncthreads();

        // ---- A fragments: M=32 (rows ra, ra+8, ra+16, ra+24) ----
        const int ra = wid * 32 + rg;
        unsigned a[32];
#pragma unroll
        for (int b = 0; b < 2; ++b)
#pragma unroll
            for (int ks = 0; ks < 4; ++ks) {
                int rbase = (ra + 16 * b) * 36;
                a[b * 16 + ks * 4 + 0] = zhw[rbase + q + ks * 8];
                a[b * 16 + ks * 4 + 1] = zhw[rbase + 8 * 36 + q + ks * 8];
                a[b * 16 + ks * 4 + 2] = zhw[rbase + q + 4 + ks * 8];
                a[b * 16 + ks * 4 + 3] = zhw[rbase + 8 * 36 + q + 4 + ks * 8];
            }

        // ---- pass 1: fast mins (score = ee - 2 z.e, fp16), 2 tiles per iter ----
        unsigned mm0 = 0x7BFF7BFFu, mm1 = 0x7BFF7BFFu, mm2 = 0x7BFF7BFFu, mm3 = 0x7BFF7BFFu;
#pragma unroll 1
        for (int t = 0; t < NTILES; t += 2) {
            uint2 ew = *(const uint2*)(eeq + q * 64 + t);   // einit for tiles t, t+1
#pragma unroll
            for (int s2 = 0; s2 < 2; ++s2) {
                unsigned einit = s2 ? ew.y : ew.x;
                unsigned c01, c23, c45, c67;
                TILE_BODY(t + s2, einit, c01, c23, c45, c67);
                mm0 = hmin2u(mm0, c01);
                mm1 = hmin2u(mm1, c23);
                mm2 = hmin2u(mm2, c45);
                mm3 = hmin2u(mm3, c67);
                unsigned tw = hmin2u(hmin2u(c01, c23), hmin2u(c45, c67));
                __half2 th = *(__half2*)&tw;
                float tm = fminf(__low2float(th), __high2float(th));
                tm = fminf(tm, __shfl_xor_sync(0xffffffffu, tm, 1));
                tm = fminf(tm, __shfl_xor_sync(0xffffffffu, tm, 2));
                if (q == 0) tminp[(wid * NTILES + t + s2) * 8 + rg] = __float2half(tm);
            }
        }
        __syncwarp();

        __half2 h0 = *(__half2*)&mm0, h1 = *(__half2*)&mm1;
        __half2 h2 = *(__half2*)&mm2, h3 = *(__half2*)&mm3;
        float mr0 = fminf(__low2float(h0), __high2float(h0));
        float mr1 = fminf(__low2float(h1), __high2float(h1));
        float mr2 = fminf(__low2float(h2), __high2float(h2));
        float mr3 = fminf(__low2float(h3), __high2float(h3));
#pragma unroll
        for (int off = 1; off < 4; off <<= 1) {
            mr0 = fminf(mr0, __shfl_xor_sync(0xffffffffu, mr0, off));
            mr1 = fminf(mr1, __shfl_xor_sync(0xffffffffu, mr1, off));
            mr2 = fminf(mr2, __shfl_xor_sync(0xffffffffu, mr2, off));
            mr3 = fminf(mr3, __shfl_xor_sync(0xffffffffu, mr3, off));
        }
        const float t0 = mr0 + MARGIN, t1 = mr1 + MARGIN;
        const float t2 = mr2 + MARGIN, t3 = mr3 + MARGIN;
        const float thrq = fmaxf(fmaxf(t0, t1), fmaxf(t2, t3));

        // ---- pass 2: pruned recompute, enqueue candidates (call-free) ----
#define PUSH(rowv, jv) do {                                                       \
        unsigned pk_ = (unsigned)(rowv) | ((unsigned)(jv) << 9);                  \
        int qi_ = atomicAdd(qcnt + wid, 1);                                       \
        if (qi_ < QCAP) que[wid * QCAP + qi_] = pk_;                              \
        else wflg[wid] = 1;                                                       \
    } while (0)

#pragma unroll 1
        for (int t = 0; t < NTILES; ++t) {
            float tm = __half2float(tminp[(wid * NTILES + t) * 8 + rg]);
            if (!__any_sync(0xffffffffu, tm <= thrq)) continue;

            unsigned einit = eeq[q * 64 + t];
            unsigned c01, c23, c45, c67;
            TILE_BODY(t, einit, c01, c23, c45, c67);
            __half2 p0 = *(__half2*)&c01, p1 = *(__half2*)&c23;
            __half2 p2 = *(__half2*)&c45, p3 = *(__half2*)&c67;
            int jb = t * 8 + 2 * q;
            if (__low2float(p0) <= t0) PUSH(ra, jb);
            if (__high2float(p0) <= t0) PUSH(ra, jb + 1);
            if (__low2float(p1) <= t1) PUSH(ra + 8, jb);
            if (__high2float(p1) <= t1) PUSH(ra + 8, jb + 1);
            if (__low2float(p2) <= t2) PUSH(ra + 16, jb);
            if (__high2float(p2) <= t2) PUSH(ra + 16, jb + 1);
            if (__low2float(p3) <= t3) PUSH(ra + 24, jb);
            if (__high2float(p3) <= t3) PUSH(ra + 24, jb + 1);
        }
#undef PUSH

        // ---- drain: 32 lanes rescore distinct candidates ----
        __syncwarp();
        int n = *(volatile int*)(qcnt + wid);
        int ncap = n < QCAP ? n : QCAP;
        for (int base = 0; base < ncap; base += 32) {
            int k2 = base + lane;
            if (k2 < ncap) exact_commit(que[wid * QCAP + k2], z, cb, blockRow, zzs, eef, minr);
        }
        if (wflg[wid]) {
            // Unreachable in practice; provably-correct fallback: exhaustive
            // rescore of this warp's 32 rows against all codes.
            for (int rr = 0; rr < 32; ++rr) {
                int row = wid * 32 + rr;
                for (int j = lane; j < Kc; j += 32)
                    exact_commit((unsigned)row | ((unsigned)j << 9), z, cb, blockRow, zzs, eef, minr);
            }
        }
        __syncthreads();

        // ---- gather + write both tuple halves ----
#pragma unroll
        for (int it = 0; it < 2; ++it) {
            int row = (tid >> 1) + it * 256, hh = tid & 1;
            int j = (int)(unsigned)(minr[row] & 0xFFFFFFFFull);
            size_t g = blockRow + row;
            const float4* s4 = (const float4*)(cb + (size_t)j * Dm + hh * 32);
            float4* o1 = (float4*)(out + g * Dm + hh * 32);
            float4* o2 = (half > 0) ? (float4*)(out + half + g * Dm + hh * 32) : nullptr;
#pragma unroll
            for (int i = 0; i < 8; ++i) {
                float4 tv = s4[i];
                o1[i] = tv;
                if (o2) o2[i] = tv;
            }
        }
    }
}

extern "C" void kernel_launch(void* const* d_in, const int* in_sizes, int n_in,
                              void* d_out, int out_size) {
    const float* z = (const float*)d_in[0];
    const float* cb = (const float*)d_in[1];
    float* out = (float*)d_out;
    const int N = in_sizes[0] / Dm;                      // 131072
    const int nblk = N / ROWS_CTA;                       // 256
    long long half = ((long long)out_size >= 2LL * N * Dm) ? (long long)out_size / 2 : 0;

    cudaFuncSetAttribute(vq_kernel, cudaFuncAttributeMaxDynamicSharedMemorySize, SM_TOTAL);
    int grid = nblk < GRID ? nblk : GRID;
    vq_kernel<<<grid, THREADS, SM_TOTAL>>>(z, cb, out, half, nblk);
}